// round 2
// baseline (speedup 1.0000x reference)
#include <cuda_runtime.h>
#include <cstdint>
#include <cstddef>

// Problem dims (fixed)
#define M_ROWS 16384
#define CDIM 512
#define HDIM 512
#define DDIM 1024
#define EHID 1024   // C*E

// ---------------- scratch (device globals; no allocation allowed) ----------------
__device__ float g_XU[M_ROWS * HDIM];
__device__ float g_Hs[M_ROWS * HDIM];
__device__ float g_T1[M_ROWS * DDIM];
__device__ float g_T2[M_ROWS * DDIM];
__device__ float g_Xb[M_ROWS * CDIM];
__device__ float g_psum[128 * CDIM];
__device__ float g_pmax[128 * CDIM];
__device__ float g_avg[CDIM];
__device__ float g_mx[CDIM];
__device__ float g_att[CDIM];

__device__ __forceinline__ float sigf(float x) { return 1.0f / (1.0f + __expf(-x)); }

// =====================================================================
// Persistent cluster RNN: h_t = sigmoid(XU[t] + h_{t-1} @ W)
// 8-CTA cluster; W held in registers (64 fp32/thread as 32 packed f32x2);
// h double-buffered in SMEM, broadcast via DSMEM stores; barrier.cluster/step.
// Thread map: col = rank*64 + (tid>>3); part = tid&7 covers rows part*64..+63.
// h layout padded: row r lives at (r>>6)*68 + (r&63)  (bank-conflict-free LDS.128)
// =====================================================================
#define RNN_NCTA 8

__global__ void __cluster_dims__(RNN_NCTA, 1, 1) __launch_bounds__(512, 1)
rnn_kernel(const float* __restrict__ XU, const float* __restrict__ W,
           float* __restrict__ Hs, int T)
{
    __shared__ float hbuf[2][8 * 68];

    const int tid = threadIdx.x;
    const int part = tid & 7;          // 0..7  (row chunk)
    const int col_local = tid >> 3;    // 0..63
    const int rank = blockIdx.x;       // one cluster == whole grid
    const int col = rank * 64 + col_local;

    // Load W slice into packed register pairs: rows part*64 + 2q, 2q+1 ; column col
    unsigned long long wp[32];
    const int rbase = part * 64;
#pragma unroll
    for (int q = 0; q < 32; q++) {
        float w0 = W[(size_t)(rbase + 2 * q) * HDIM + col];
        float w1 = W[(size_t)(rbase + 2 * q + 1) * HDIM + col];
        asm("mov.b64 %0, {%1,%2};" : "=l"(wp[q]) : "f"(w0), "f"(w1));
    }

    // zero both h buffers locally
    for (int i = tid; i < 2 * 8 * 68; i += 512) hbuf[0][i] = 0.0f;

    // Precompute remote SMEM addresses for the h_new scatter (part==0 lanes only)
    uint32_t raddr[2][RNN_NCTA];
    if (part == 0) {
        const int idx = (col >> 6) * 68 + (col & 63);
#pragma unroll
        for (int b = 0; b < 2; b++) {
            uint32_t la = (uint32_t)__cvta_generic_to_shared(&hbuf[b][idx]);
#pragma unroll
            for (int c = 0; c < RNN_NCTA; c++) {
                asm("mapa.shared::cluster.u32 %0, %1, %2;"
                    : "=r"(raddr[b][c]) : "r"(la), "r"(c));
            }
        }
    }

    asm volatile("barrier.cluster.arrive.aligned;" ::: "memory");
    asm volatile("barrier.cluster.wait.aligned;" ::: "memory");

    for (int t = 0; t < T; t++) {
        const int cur = t & 1;
        const int nxt = cur ^ 1;

        // prefetch this step's xu early (only consumed after the matvec)
        float xu = 0.0f;
        if (part == 0) xu = __ldg(&XU[(size_t)t * HDIM + col]);

        const ulonglong2* hp =
            (const ulonglong2*)(&hbuf[cur][part * 68]);

        unsigned long long acc0 = 0ull, acc1 = 0ull;  // bit pattern == (0.f,0.f)
#pragma unroll
        for (int k = 0; k < 16; k++) {
            ulonglong2 hv = hp[k];
            asm("fma.rn.f32x2 %0, %1, %2, %3;"
                : "=l"(acc0) : "l"(hv.x), "l"(wp[2 * k]), "l"(acc0));
            asm("fma.rn.f32x2 %0, %1, %2, %3;"
                : "=l"(acc1) : "l"(hv.y), "l"(wp[2 * k + 1]), "l"(acc1));
        }
        float s0, s1, s2, s3;
        asm("mov.b64 {%0,%1}, %2;" : "=f"(s0), "=f"(s1) : "l"(acc0));
        asm("mov.b64 {%0,%1}, %2;" : "=f"(s2), "=f"(s3) : "l"(acc1));
        float acc = (s0 + s1) + (s2 + s3);

        // reduce over the 8 part-lanes (lanes xor 1,2,4 stay in the 8-group)
        acc += __shfl_xor_sync(0xffffffffu, acc, 1);
        acc += __shfl_xor_sync(0xffffffffu, acc, 2);
        acc += __shfl_xor_sync(0xffffffffu, acc, 4);

        if (part == 0) {
            float hn = sigf(xu + acc);
            Hs[(size_t)t * HDIM + col] = hn;  // fire-and-forget
#pragma unroll
            for (int c = 0; c < RNN_NCTA; c++) {
                asm volatile("st.shared::cluster.f32 [%0], %1;"
                             :: "r"(raddr[nxt][c]), "f"(hn) : "memory");
            }
        }
        // arrive has release semantics; wait has acquire: orders the DSMEM stores
        asm volatile("barrier.cluster.arrive.aligned;" ::: "memory");
        asm volatile("barrier.cluster.wait.aligned;" ::: "memory");
    }
}

// =====================================================================
// SIMT fp32 GEMM: C = act( (A [+A2]) (*ascale_k) @ B )
// A: [M,K] row-major, B: [K,N] row-major, C: [M,N].
// 128x128 tile, BK=8, 256 threads, 8x8 per thread, prefetched tiles.
// All dims are multiples of the tile sizes in this problem (no bounds checks).
// =====================================================================
#define BM 128
#define BN 128
#define BK 8

__global__ __launch_bounds__(256)
void gemm_kernel(const float* __restrict__ A, const float* __restrict__ A2,
                 const float* __restrict__ ascale,
                 const float* __restrict__ B, float* __restrict__ C,
                 int M, int N, int K, int act)
{
    __shared__ float As[BK][BM];
    __shared__ float Bs[BK][BN];

    const int tid = threadIdx.x;
    const int n0 = blockIdx.x * BN;
    const int m0 = blockIdx.y * BM;
    const int tx = tid & 15;   // n dir
    const int ty = tid >> 4;   // m dir

    const int arow = tid >> 1;           // 0..127
    const int akk  = (tid & 1) * 4;      // 0 or 4
    const int brow = tid >> 5;           // 0..7
    const int bcol = (tid & 31) * 4;     // 0..124

    const float* Ap  = A + (size_t)(m0 + arow) * K + akk;
    const float* A2p = A2 ? (A2 + (size_t)(m0 + arow) * K + akk) : nullptr;
    const float* Bp  = B + (size_t)brow * N + n0 + bcol;

    float acc[8][8];
#pragma unroll
    for (int i = 0; i < 8; i++)
#pragma unroll
        for (int j = 0; j < 8; j++) acc[i][j] = 0.0f;

    // initial prefetch
    float4 av = *(const float4*)(Ap);
    if (A2p) {
        float4 a2 = *(const float4*)(A2p);
        av.x += a2.x; av.y += a2.y; av.z += a2.z; av.w += a2.w;
    }
    if (ascale) {
        av.x *= ascale[akk]; av.y *= ascale[akk + 1];
        av.z *= ascale[akk + 2]; av.w *= ascale[akk + 3];
    }
    float4 bv = *(const float4*)(Bp);

    for (int k0 = 0; k0 < K; k0 += BK) {
        __syncthreads();
        As[akk + 0][arow] = av.x;
        As[akk + 1][arow] = av.y;
        As[akk + 2][arow] = av.z;
        As[akk + 3][arow] = av.w;
        *(float4*)&Bs[brow][bcol] = bv;
        __syncthreads();

        const int kn = k0 + BK;
        if (kn < K) {
            av = *(const float4*)(Ap + kn);
            if (A2p) {
                float4 a2 = *(const float4*)(A2p + kn);
                av.x += a2.x; av.y += a2.y; av.z += a2.z; av.w += a2.w;
            }
            if (ascale) {
                av.x *= ascale[kn + akk]; av.y *= ascale[kn + akk + 1];
                av.z *= ascale[kn + akk + 2]; av.w *= ascale[kn + akk + 3];
            }
            bv = *(const float4*)(Bp + (size_t)kn * N);
        }

#pragma unroll
        for (int kk = 0; kk < BK; kk++) {
            float a[8], b[8];
            *(float4*)(a)     = *(const float4*)&As[kk][ty * 8];
            *(float4*)(a + 4) = *(const float4*)&As[kk][ty * 8 + 4];
            *(float4*)(b)     = *(const float4*)&Bs[kk][tx * 8];
            *(float4*)(b + 4) = *(const float4*)&Bs[kk][tx * 8 + 4];
#pragma unroll
            for (int i = 0; i < 8; i++)
#pragma unroll
                for (int j = 0; j < 8; j++) acc[i][j] += a[i] * b[j];
        }
    }

#pragma unroll
    for (int i = 0; i < 8; i++) {
        float4 o0, o1;
        float* r = &acc[i][0];
        if (act) {
#pragma unroll
            for (int j = 0; j < 8; j++) r[j] = sigf(r[j]);
        }
        o0.x = r[0]; o0.y = r[1]; o0.z = r[2]; o0.w = r[3];
        o1.x = r[4]; o1.y = r[5]; o1.z = r[6]; o1.w = r[7];
        float* cp = C + (size_t)(m0 + ty * 8 + i) * N + n0 + tx * 8;
        *(float4*)(cp)     = o0;
        *(float4*)(cp + 4) = o1;
    }
}

// =====================================================================
// Column-wise mean/max over M rows (two stage)
// =====================================================================
__global__ __launch_bounds__(512)
void reduce_partial(const float* __restrict__ Y, float* __restrict__ psum,
                    float* __restrict__ pmax)
{
    const int c = threadIdx.x;
    const int b = blockIdx.x;
    float s = 0.0f, mx = -3.4e38f;
    const int r0 = b * (M_ROWS / 128);
#pragma unroll 4
    for (int r = r0; r < r0 + (M_ROWS / 128); r++) {
        float v = Y[(size_t)r * CDIM + c];
        s += v;
        mx = fmaxf(mx, v);
    }
    psum[b * CDIM + c] = s;
    pmax[b * CDIM + c] = mx;
}

__global__ __launch_bounds__(512)
void reduce_final(const float* __restrict__ psum, const float* __restrict__ pmax,
                  float* __restrict__ avg, float* __restrict__ mxo)
{
    const int c = threadIdx.x;
    float s = 0.0f, m = -3.4e38f;
#pragma unroll 4
    for (int b = 0; b < 128; b++) {
        s += psum[b * CDIM + c];
        m = fmaxf(m, pmax[b * CDIM + c]);
    }
    avg[c] = s * (1.0f / (float)M_ROWS);
    mxo[c] = m;
}

// =====================================================================
// Channel-attention MLP: att = sigmoid(relu(avg@Wa1)@Wa2 + relu(mx@Wa1)@Wa2)
// Single block, 512 threads. Writes to out region AND scratch (for GEMM fold).
// =====================================================================
__global__ __launch_bounds__(512)
void att_kernel(const float* __restrict__ avg, const float* __restrict__ mx,
                const float* __restrict__ Wa1j, const float* __restrict__ Wa2j,
                float* __restrict__ att_out, float* __restrict__ att_scr)
{
    __shared__ float sa[CDIM], sm[CDIM], hsum[EHID];
    const int t = threadIdx.x;
    sa[t] = avg[t];
    sm[t] = mx[t];
    __syncthreads();

    for (int h = t; h < EHID; h += 512) {
        float a1 = 0.0f, a2 = 0.0f;
        for (int k = 0; k < CDIM; k++) {
            float w = Wa1j[(size_t)k * EHID + h];
            a1 += sa[k] * w;
            a2 += sm[k] * w;
        }
        hsum[h] = fmaxf(a1, 0.0f) + fmaxf(a2, 0.0f);
    }
    __syncthreads();

    float z = 0.0f;
    for (int k = 0; k < EHID; k++) z += hsum[k] * Wa2j[(size_t)k * CDIM + t];
    float s = sigf(z);
    att_out[t] = s;
    att_scr[t] = s;
}

// =====================================================================
// y_hat = X @ Wd  ([16384,512] @ [512,1]); one warp per row.
// =====================================================================
__global__ __launch_bounds__(256)
void yhat_kernel(const float* __restrict__ Xf, const float* __restrict__ Wd,
                 float* __restrict__ y)
{
    __shared__ float w[CDIM];
    const int tid = threadIdx.x;
    for (int i = tid; i < CDIM; i += 256) w[i] = Wd[i];
    __syncthreads();
    const int warp = tid >> 5, lane = tid & 31;
    const int r = blockIdx.x * 8 + warp;
    float s = 0.0f;
#pragma unroll 4
    for (int k = lane; k < CDIM; k += 32) s += Xf[(size_t)r * CDIM + k] * w[k];
#pragma unroll
    for (int off = 16; off; off >>= 1) s += __shfl_xor_sync(0xffffffffu, s, off);
    if (lane == 0) y[r] = s;
}

// =====================================================================
// Launch sequence
// =====================================================================
extern "C" void kernel_launch(void* const* d_in, const int* in_sizes, int n_in,
                              void* d_out, int out_size)
{
    const float* X   = (const float*)d_in[0];
    const float* U   = (const float*)d_in[1];
    const float* W   = (const float*)d_in[2];
    const float* V   = (const float*)d_in[3];
    const float* Wd1 = (const float*)d_in[4];
    const float* Wd2 = (const float*)d_in[5];
    const float* Wd3 = (const float*)d_in[6];
    const float* Wd  = (const float*)d_in[7];
    const float* Wa1 = (const float*)d_in[8];
    const float* Wa2 = (const float*)d_in[9];

    float* out = (float*)d_out;
    float* y_hat   = out;                       // [16384]
    float* att_out = out + M_ROWS;              // [2*512]
    float* data_out = out + M_ROWS + 2 * CDIM;  // [2*16384*512]

    float *p_XU, *p_Hs, *p_T1, *p_T2, *p_Xb, *p_ps, *p_pm, *p_avg, *p_mx, *p_att;
    cudaGetSymbolAddress((void**)&p_XU, g_XU);
    cudaGetSymbolAddress((void**)&p_Hs, g_Hs);
    cudaGetSymbolAddress((void**)&p_T1, g_T1);
    cudaGetSymbolAddress((void**)&p_T2, g_T2);
    cudaGetSymbolAddress((void**)&p_Xb, g_Xb);
    cudaGetSymbolAddress((void**)&p_ps, g_psum);
    cudaGetSymbolAddress((void**)&p_pm, g_pmax);
    cudaGetSymbolAddress((void**)&p_avg, g_avg);
    cudaGetSymbolAddress((void**)&p_mx, g_mx);
    cudaGetSymbolAddress((void**)&p_att, g_att);

    const dim3 blk(256);
    const dim3 g512(CDIM / BN, M_ROWS / BM);   // N=512
    const dim3 g1024(DDIM / BN, M_ROWS / BM);  // N=1024

    for (int j = 0; j < 2; j++) {
        const float* Ain = (j == 0) ? X : p_Xb;
        const float* Ares = (j == 0) ? nullptr : X;

        // XU = (Ain [+ X]) @ U
        gemm_kernel<<<g512, blk>>>(Ain, Ares, nullptr, U, p_XU,
                                   M_ROWS, HDIM, CDIM, 0);

        // sequential RNN over 16384 steps (persistent 8-CTA cluster)
        rnn_kernel<<<RNN_NCTA, 512>>>(p_XU, W, p_Hs, M_ROWS);

        // data_j = sigmoid(Hs @ V)  (written straight into output)
        float* Yj = data_out + (size_t)j * M_ROWS * CDIM;
        gemm_kernel<<<g512, blk>>>(p_Hs, nullptr, nullptr, V, Yj,
                                   M_ROWS, CDIM, HDIM, 1);

        // channel stats + attention
        reduce_partial<<<128, 512>>>(Yj, p_ps, p_pm);
        reduce_final<<<1, 512>>>(p_ps, p_pm, p_avg, p_mx);
        att_kernel<<<1, 512>>>(p_avg, p_mx,
                               Wa1 + (size_t)j * CDIM * EHID,
                               Wa2 + (size_t)j * EHID * CDIM,
                               att_out + j * CDIM, p_att);

        // dense stack, att folded as A-column scale into the first GEMM
        gemm_kernel<<<g1024, blk>>>(Yj, nullptr, p_att, Wd1, p_T1,
                                    M_ROWS, DDIM, CDIM, 1);
        gemm_kernel<<<g1024, blk>>>(p_T1, nullptr, nullptr, Wd2, p_T2,
                                    M_ROWS, DDIM, DDIM, 1);
        gemm_kernel<<<g512, blk>>>(p_T2, nullptr, nullptr, Wd3, p_Xb,
                                   M_ROWS, CDIM, DDIM, 1);
    }

    // y_hat = Xb @ Wd
    yhat_kernel<<<M_ROWS / 8, 256>>>(p_Xb, Wd, y_hat);
}